// round 3
// baseline (speedup 1.0000x reference)
#include <cuda_runtime.h>
#include <math.h>

#define KTOT 32
#define KIND 16
#define KMLP 16
#define DH   64
#define DISTMAX 1.0f
#define MAXNODES 100001
#define MAXIV 65
#define WARPS 8
#define FULLMASK 0xffffffffu

// ---------------- device scratch ----------------
__device__ int   g_row_ptr[MAXNODES + 2];
__device__ float g_B[MAXIV + 1];
__device__ int   g_niv;
__device__ float g_slope[MAXIV * KMLP];
__device__ float g_icept[MAXIV * KMLP];
__device__ float g_ac, g_c1, g_bc;
__device__ int   g_fast;                 // (b==2) && single-interval MLP
__device__ __align__(16) float g_gath[MAXNODES * KTOT];

__device__ __forceinline__ float ex2f(float x) {
    float r;
    asm("ex2.approx.f32 %0, %1;" : "=f"(r) : "f"(x));
    return r;
}

// ---------------- fused pre-pass: block 0 = setup, all blocks = rowptr -------
__global__ void pre_kernel(const float* __restrict__ w1, const float* __restrict__ b1,
                           const float* __restrict__ w2, const float* __restrict__ b2,
                           const float* __restrict__ a,  const float* __restrict__ b,
                           const int* __restrict__ recv, int n_edges, int n_nodes) {
    int i = blockIdx.x * blockDim.x + threadIdx.x;
    if (i <= n_nodes) {
        int lo = 0, hi = n_edges;
        while (lo < hi) {
            int mid = (lo + hi) >> 1;
            if (recv[mid] < i) lo = mid + 1; else hi = mid;
        }
        g_row_ptr[i] = lo;
    }
    if (blockIdx.x != 0) return;

    __shared__ float sw1[DH], sb1[DH], sw2[DH * KMLP], sb2[KMLP];
    __shared__ float bps[DH];
    __shared__ int   nbp;
    __shared__ float B[MAXIV + 1];
    __shared__ int   niv_s;
    int tid = threadIdx.x;
    for (int k = tid; k < DH; k += blockDim.x) { sw1[k] = w1[k]; sb1[k] = b1[k]; }
    for (int k = tid; k < DH * KMLP; k += blockDim.x) sw2[k] = w2[k];
    if (tid < KMLP) sb2[tid] = b2[tid];
    if (tid == 0) {
        float ac = fminf(fmaxf(a[0], 0.f), 1.f);
        g_ac = ac; g_c1 = 1.f - ac;
        float bc = fabsf(b[0]);
        g_bc = bc;
        nbp = 0;
    }
    __syncthreads();
    if (tid < DH) {
        float w = sw1[tid], bb = sb1[tid];
        if (w != 0.f) {
            float t = -bb / w;
            if (t > 0.f && t < DISTMAX) { int k = atomicAdd(&nbp, 1); bps[k] = t; }
        }
    }
    __syncthreads();
    if (tid == 0) {
        for (int k = 1; k < nbp; k++) {
            float v = bps[k]; int j = k - 1;
            while (j >= 0 && bps[j] > v) { bps[j + 1] = bps[j]; j--; }
            bps[j + 1] = v;
        }
        B[0] = 0.f;
        for (int k = 0; k < nbp; k++) B[k + 1] = bps[k];
        B[nbp + 1] = DISTMAX;
        niv_s = nbp + 1;
        g_niv = niv_s;
        g_fast = (g_bc == 2.0f && niv_s == 1) ? 1 : 0;
    }
    __syncthreads();
    int niv = niv_s;
    for (int k = tid; k <= niv; k += blockDim.x) g_B[k] = B[k];
    for (int idx = tid; idx < niv * KMLP; idx += blockDim.x) {
        int iv = idx / KMLP, k = idx % KMLP;
        float dm = 0.5f * (B[iv] + B[iv + 1]);
        float sl = 0.f, ic = 0.f;
        for (int h = 0; h < DH; h++) {
            float w = sw1[h], bb = sb1[h];
            if (w * dm + bb > 0.f) {
                float w2v = sw2[h * KMLP + k];
                sl += w * w2v;
                ic += bb * w2v;
            }
        }
        g_slope[idx] = sl;
        g_icept[idx] = ic + sb2[k];
    }
}

// ---------------- gather kernel: one warp per node, lane = feature -----------
__global__ void __launch_bounds__(WARPS * 32)
gather_kernel(const float* __restrict__ nodes, const float* __restrict__ dist,
              const float* __restrict__ pad,   const int* __restrict__ send,
              int n_nodes) {
    __shared__ float sB[MAXIV + 1];
    __shared__ float sSl[MAXIV * KMLP], sIc[MAXIV * KMLP];

    int tid = threadIdx.x;
    int niv = g_niv;
    // stage fallback tables (cheap; fast path ignores them)
    for (int i = tid; i <= niv; i += blockDim.x) sB[i] = g_B[i];
    for (int i = tid; i < niv * KMLP; i += blockDim.x) { sSl[i] = g_slope[i]; sIc[i] = g_icept[i]; }
    __syncthreads();

    const int w = tid >> 5, lane = tid & 31;
    int n = blockIdx.x * WARPS + w;
    if (n >= n_nodes) return;

    const float ac = g_ac, c1 = g_c1;
    const int   fast = g_fast;

    const float binw = DISTMAX / (float)KIND;
    const float lo_b = (float)lane * binw;     // lanes>=16: lo_b>=1.0 -> never in bin
    const float hi_b = lo_b + binw;
    const int mk = lane & (KMLP - 1);

    float nval = nodes[n * KTOT + lane];
    float nra  = ac * nval;
    int start = g_row_ptr[n], end = g_row_ptr[n + 1];
    const float* nl = nodes + lane;

    float cnt = 0.f, ai = 0.f, am = 0.f, s = 0.f;

    if (fast) {
        // per-lane constant softmax base: vb >= max v over d in [0, DISTMAX]
        const float L2E = 1.4426950408889634f;
        float slc = sSl[mk], icc = sIc[mk];
        float vb  = fmaxf(icc, fmaf(slc, DISTMAX, icc));
        float sl2 = slc * L2E, ic2 = (icc - vb) * L2E;

        for (int base = start; base < end; base += 32) {
            int e = base + lane;
            bool vld = e < end;
            float dL = vld ? __ldg(&dist[e]) : 0.f;
            float pL = vld ? __ldg(&pad[e])  : 0.f;
            int   sL = vld ? __ldg(&send[e]) : 0;
            int nb = min(32, end - base);

            int j = 0;
            for (; j + 4 <= nb; j += 4) {
                int   sid[4]; float dd[4], pp[4], ns[4];
                #pragma unroll
                for (int u = 0; u < 4; u++) {
                    sid[u] = __shfl_sync(FULLMASK, sL, j + u);
                    dd[u]  = __shfl_sync(FULLMASK, dL, j + u);
                    pp[u]  = __shfl_sync(FULLMASK, pL, j + u);
                }
                #pragma unroll
                for (int u = 0; u < 4; u++)
                    ns[u] = __ldg(nl + sid[u] * KTOT);
                #pragma unroll
                for (int u = 0; u < 4; u++) {
                    float d  = dd[u];
                    float t  = fmaf(-c1, ns[u], nra);
                    float we = pp[u] * (t * t);
                    bool inb = (d > lo_b) && (d < hi_b);
                    if (inb) { cnt += 1.f; ai += we; }
                    float ex = ex2f(fmaf(sl2, d, ic2));
                    s += ex;
                    am = fmaf(ex, we, am);
                }
            }
            for (; j < nb; j++) {
                int   sid = __shfl_sync(FULLMASK, sL, j);
                float d   = __shfl_sync(FULLMASK, dL, j);
                float pp  = __shfl_sync(FULLMASK, pL, j);
                float nsv = __ldg(nl + sid * KTOT);
                float t   = fmaf(-c1, nsv, nra);
                float we  = pp * (t * t);
                bool inb = (d > lo_b) && (d < hi_b);
                if (inb) { cnt += 1.f; ai += we; }
                float ex = ex2f(fmaf(sl2, d, ic2));
                s += ex;
                am = fmaf(ex, we, am);
            }
        }
    } else {
        // generic fallback: any b, multi-interval PWL, online softmax
        const float bc = g_bc;
        float m = -INFINITY;
        for (int e = start; e < end; e++) {
            float d   = __ldg(&dist[e]);
            float pp  = __ldg(&pad[e]);
            int   sid = __ldg(&send[e]);
            float nsv = __ldg(nl + sid * KTOT);
            float t   = fmaf(-c1, nsv, nra);
            float we  = pp * powf(fabsf(t), bc);
            bool inb = (d > lo_b) && (d < hi_b);
            if (inb) { cnt += 1.f; ai += we; }
            int lo = 0, hi = niv - 1;
            while (lo < hi) {
                int mid = (lo + hi + 1) >> 1;
                if (d >= sB[mid]) lo = mid; else hi = mid - 1;
            }
            float v  = fmaf(sSl[lo * KMLP + mk], d, sIc[lo * KMLP + mk]);
            float nm = fmaxf(m, v);
            float sc = __expf(m - nm);
            float p  = __expf(v - nm);
            s   = fmaf(s, sc, p);
            am  = fmaf(am, sc, p * we);
            m   = nm;
        }
    }

    float g;
    if (lane < KIND) g = __fdividef(ai, cnt + 1e-5f);
    else             g = (s > 0.f) ? __fdividef(am, s) : 0.f;
    g_gath[n * KTOT + lane] = g;
}

// ---------------- epilogue: out = relu(nodes@WS + gath@WG + bg) --------------
// warp handles 8 nodes; lane k holds weight columns WS[:,k], WG[:,k] in regs
__global__ void __launch_bounds__(WARPS * 32)
epi_kernel(const float* __restrict__ nodes, const float* __restrict__ wgs,
           const float* __restrict__ wgg,   const float* __restrict__ bgg,
           float* __restrict__ out, int n_nodes) {
    __shared__ float4 sX[WARPS][8][8];
    __shared__ float4 sG[WARPS][8][8];

    int tid = threadIdx.x;
    int w = tid >> 5, lane = tid & 31;

    float ws[KTOT], wg[KTOT];
    #pragma unroll
    for (int j = 0; j < KTOT; j++) {
        ws[j] = __ldg(&wgs[j * KTOT + lane]);
        wg[j] = __ldg(&wgg[j * KTOT + lane]);
    }
    float bgk = __ldg(&bgg[lane]);

    int wid = blockIdx.x * WARPS + w;
    int n0 = wid * 8;
    if (n0 >= n_nodes) return;

    const float4* x4 = (const float4*)nodes;
    const float4* g4 = (const float4*)g_gath;
    int lim4 = n_nodes * 8;

    // stage 8 node rows of x and g (64 float4 each, 2 per lane)
    {
        int i1 = lane >> 3, j1 = lane & 7;
        int idxA = n0 * 8 + lane, idxB = idxA + 32;
        float4 z = make_float4(0.f, 0.f, 0.f, 0.f);
        sX[w][i1][j1]     = (idxA < lim4) ? __ldg(&x4[idxA]) : z;
        sX[w][i1 + 4][j1] = (idxB < lim4) ? __ldg(&x4[idxB]) : z;
        sG[w][i1][j1]     = (idxA < lim4) ? __ldg(&g4[idxA]) : z;
        sG[w][i1 + 4][j1] = (idxB < lim4) ? __ldg(&g4[idxB]) : z;
    }
    __syncwarp();

    #pragma unroll
    for (int i = 0; i < 8; i++) {
        int n = n0 + i;
        if (n >= n_nodes) break;
        float o = bgk;
        #pragma unroll
        for (int j4 = 0; j4 < 8; j4++) {
            float4 xv = sX[w][i][j4];   // broadcast LDS.128
            float4 gv = sG[w][i][j4];
            o = fmaf(xv.x, ws[j4 * 4 + 0], o);
            o = fmaf(xv.y, ws[j4 * 4 + 1], o);
            o = fmaf(xv.z, ws[j4 * 4 + 2], o);
            o = fmaf(xv.w, ws[j4 * 4 + 3], o);
            o = fmaf(gv.x, wg[j4 * 4 + 0], o);
            o = fmaf(gv.y, wg[j4 * 4 + 1], o);
            o = fmaf(gv.z, wg[j4 * 4 + 2], o);
            o = fmaf(gv.w, wg[j4 * 4 + 3], o);
        }
        out[n * KTOT + lane] = fmaxf(o, 0.f);
    }
}

// ---------------- launch ----------------
extern "C" void kernel_launch(void* const* d_in, const int* in_sizes, int n_in,
                              void* d_out, int out_size) {
    const float* nodes     = (const float*)d_in[0];
    const float* distance  = (const float*)d_in[1];
    const float* padding   = (const float*)d_in[2];
    const int*   receivers = (const int*)d_in[3];
    const int*   senders   = (const int*)d_in[4];
    const float* w1        = (const float*)d_in[5];
    const float* b1        = (const float*)d_in[6];
    const float* w2        = (const float*)d_in[7];
    const float* b2        = (const float*)d_in[8];
    const float* a         = (const float*)d_in[9];
    const float* b         = (const float*)d_in[10];
    const float* wgs       = (const float*)d_in[11];
    const float* wgg       = (const float*)d_in[12];
    const float* bgg       = (const float*)d_in[13];

    int n_nodes = in_sizes[0] / KTOT;
    int n_edges = in_sizes[1];

    pre_kernel<<<(n_nodes + 1 + 255) / 256, 256>>>(w1, b1, w2, b2, a, b,
                                                   receivers, n_edges, n_nodes);
    int gblocks = (n_nodes + WARPS - 1) / WARPS;
    gather_kernel<<<gblocks, WARPS * 32>>>(nodes, distance, padding, senders, n_nodes);

    int nwarps = (n_nodes + 7) / 8;
    int eblocks = (nwarps + WARPS - 1) / WARPS;
    epi_kernel<<<eblocks, WARPS * 32>>>(nodes, wgs, wgg, bgg, (float*)d_out, n_nodes);
}

// round 4
// speedup vs baseline: 1.4870x; 1.4870x over previous
#include <cuda_runtime.h>
#include <math.h>

#define KTOT 32
#define KIND 16
#define KMLP 16
#define DH   64
#define DISTMAX 1.0f
#define MAXNODES 100001
#define MAXEDGES 1600000
#define MAXIV 65
#define WARPS 8
#define FULLMASK 0xffffffffu

// ---------------- device scratch ----------------
__device__ int   g_row_ptr[MAXNODES + 2];
__device__ float g_B[MAXIV + 1];
__device__ int   g_niv;
__device__ float g_slope[MAXIV * KMLP];
__device__ float g_icept[MAXIV * KMLP];
__device__ float g_ac, g_c1, g_bc;
__device__ int   g_fast;
__device__ __align__(16) float  g_gath[MAXNODES * KTOT];
__device__ __align__(16) float4 g_emeta[MAXEDGES];

// ---------------- packed f32x2 helpers ----------------
typedef unsigned long long u64;
__device__ __forceinline__ u64 pk2(float lo, float hi) {
    u64 r; asm("mov.b64 %0,{%1,%2};" : "=l"(r) : "f"(lo), "f"(hi)); return r;
}
__device__ __forceinline__ void upk2(u64 v, float& lo, float& hi) {
    asm("mov.b64 {%0,%1},%2;" : "=f"(lo), "=f"(hi) : "l"(v));
}
__device__ __forceinline__ u64 fma2(u64 a, u64 b, u64 c) {
    u64 r; asm("fma.rn.f32x2 %0,%1,%2,%3;" : "=l"(r) : "l"(a), "l"(b), "l"(c)); return r;
}
__device__ __forceinline__ u64 mul2(u64 a, u64 b) {
    u64 r; asm("mul.rn.f32x2 %0,%1,%2;" : "=l"(r) : "l"(a), "l"(b)); return r;
}
__device__ __forceinline__ u64 add2(u64 a, u64 b) {
    u64 r; asm("add.rn.f32x2 %0,%1,%2;" : "=l"(r) : "l"(a), "l"(b)); return r;
}
__device__ __forceinline__ float ex2f(float x) {
    float r; asm("ex2.approx.f32 %0,%1;" : "=f"(r) : "f"(x)); return r;
}

// ---------------- pre-pass: edge-parallel rowptr scatter + meta pack ---------
__global__ void pre_kernel(const float* __restrict__ w1, const float* __restrict__ b1,
                           const float* __restrict__ w2, const float* __restrict__ b2,
                           const float* __restrict__ a,  const float* __restrict__ b,
                           const float* __restrict__ dist, const float* __restrict__ pad,
                           const int* __restrict__ send,  const int* __restrict__ recv,
                           int n_edges, int n_nodes, int meta_ok) {
    int e = blockIdx.x * blockDim.x + threadIdx.x;
    if (e < n_edges) {
        int r = __ldg(&recv[e]);
        if (meta_ok)
            g_emeta[e] = make_float4(__ldg(&dist[e]), __ldg(&pad[e]),
                                     __int_as_float(__ldg(&send[e])), 0.f);
        int rp = (e == 0) ? -1 : __ldg(&recv[e - 1]);
        for (int nn = rp + 1; nn <= r; nn++) g_row_ptr[nn] = e;
        if (e == n_edges - 1)
            for (int nn = r + 1; nn <= n_nodes; nn++) g_row_ptr[nn] = n_edges;
    }
    if (blockIdx.x != 0) return;

    // ---- PWL setup (block 0) ----
    __shared__ float sw1[DH], sb1[DH], sw2[DH * KMLP], sb2[KMLP];
    __shared__ float bps[DH];
    __shared__ int   nbp;
    __shared__ float B[MAXIV + 1];
    __shared__ int   niv_s;
    int tid = threadIdx.x;
    for (int k = tid; k < DH; k += blockDim.x) { sw1[k] = w1[k]; sb1[k] = b1[k]; }
    for (int k = tid; k < DH * KMLP; k += blockDim.x) sw2[k] = w2[k];
    if (tid < KMLP) sb2[tid] = b2[tid];
    if (tid == 0) {
        float ac = fminf(fmaxf(a[0], 0.f), 1.f);
        g_ac = ac; g_c1 = 1.f - ac;
        g_bc = fabsf(b[0]);
        nbp = 0;
    }
    __syncthreads();
    if (tid < DH) {
        float w = sw1[tid], bb = sb1[tid];
        if (w != 0.f) {
            float t = -bb / w;
            if (t > 0.f && t < DISTMAX) { int k = atomicAdd(&nbp, 1); bps[k] = t; }
        }
    }
    __syncthreads();
    if (tid == 0) {
        for (int k = 1; k < nbp; k++) {
            float v = bps[k]; int j = k - 1;
            while (j >= 0 && bps[j] > v) { bps[j + 1] = bps[j]; j--; }
            bps[j + 1] = v;
        }
        B[0] = 0.f;
        for (int k = 0; k < nbp; k++) B[k + 1] = bps[k];
        B[nbp + 1] = DISTMAX;
        niv_s = nbp + 1;
        g_niv = niv_s;
        g_fast = (g_bc == 2.0f && niv_s == 1 && meta_ok) ? 1 : 0;
    }
    __syncthreads();
    int niv = niv_s;
    for (int k = tid; k <= niv; k += blockDim.x) g_B[k] = B[k];
    for (int idx = tid; idx < niv * KMLP; idx += blockDim.x) {
        int iv = idx / KMLP, k = idx % KMLP;
        float dm = 0.5f * (B[iv] + B[iv + 1]);
        float sl = 0.f, ic = 0.f;
        for (int h = 0; h < DH; h++) {
            float w = sw1[h], bb = sb1[h];
            if (w * dm + bb > 0.f) {
                float w2v = sw2[h * KMLP + k];
                sl += w * w2v;
                ic += bb * w2v;
            }
        }
        g_slope[idx] = sl;
        g_icept[idx] = ic + sb2[k];
    }
}

// ---------------- gather: warp per node, 2 edges/instr via half-warps --------
__global__ void __launch_bounds__(WARPS * 32)
gather_kernel(const float* __restrict__ nodes, const float* __restrict__ dist,
              const float* __restrict__ pad,   const int* __restrict__ send,
              int n_nodes) {
    __shared__ float sB[MAXIV + 1];
    __shared__ float sSl[MAXIV * KMLP], sIc[MAXIV * KMLP];

    int tid = threadIdx.x;
    const int w = tid >> 5, lane = tid & 31;
    const int fast = g_fast;
    const float binw = DISTMAX / (float)KIND;

    if (fast) {
        int n = blockIdx.x * WARPS + w;
        if (n >= n_nodes) return;

        const float ac = g_ac, c1 = g_c1;
        const int half = lane >> 4;
        const int f0 = (lane & 15) * 2;
        const float lo0 = (float)f0 * binw, hi0 = lo0 + binw;
        const float lo1 = hi0, hi1 = hi0 + binw;

        float sl20 = 0.f, ic20 = -1e30f, sl21 = 0.f, ic21 = -1e30f;
        if (f0 >= KIND) {
            const float L2E = 1.4426950408889634f;
            float s0 = __ldg(&g_slope[f0 - KIND]),     i0 = __ldg(&g_icept[f0 - KIND]);
            float s1 = __ldg(&g_slope[f0 - KIND + 1]), i1 = __ldg(&g_icept[f0 - KIND + 1]);
            float vb0 = fmaxf(i0, fmaf(s0, DISTMAX, i0));
            float vb1 = fmaxf(i1, fmaf(s1, DISTMAX, i1));
            sl20 = s0 * L2E; ic20 = (i0 - vb0) * L2E;
            sl21 = s1 * L2E; ic21 = (i1 - vb1) * L2E;
        }

        int start = g_row_ptr[n], end = g_row_ptr[n + 1];
        const float* nl = nodes + f0;
        u64 nr2  = __ldg((const u64*)(nodes + n * KTOT + f0));
        u64 nra2 = mul2(pk2(ac, ac), nr2);
        u64 nc1v = pk2(-c1, -c1);

        u64 cnt2 = 0ull, ai2 = 0ull, s2 = 0ull, am2 = 0ull;

        for (int e0 = start; e0 < end; e0 += 4) {
            int ea = e0 + half, eb = ea + 2;
            float va = (ea < end) ? 1.f : 0.f;
            float vbm = (eb < end) ? 1.f : 0.f;
            float4 ma = __ldg(&g_emeta[min(ea, end - 1)]);
            float4 mb = __ldg(&g_emeta[min(eb, end - 1)]);
            u64 nsa = __ldg((const u64*)(nl + __float_as_int(ma.z) * KTOT));
            u64 nsb = __ldg((const u64*)(nl + __float_as_int(mb.z) * KTOT));
            {   // edge A (lanes 0-15: e0+0 | lanes 16-31: e0+1)
                float d = ma.x, pd_ = ma.y;
                u64 t2  = fma2(nc1v, nsa, nra2);
                u64 we2 = mul2(pk2(pd_, pd_), mul2(t2, t2));
                float ind0 = (d > lo0 && d < hi0) ? va : 0.f;
                float ind1 = (d > lo1 && d < hi1) ? va : 0.f;
                u64 ind2 = pk2(ind0, ind1);
                cnt2 = add2(cnt2, ind2);
                ai2  = fma2(ind2, we2, ai2);
                float x0 = ex2f(fmaf(sl20, d, ic20)) * va;
                float x1 = ex2f(fmaf(sl21, d, ic21)) * va;
                u64 xp = pk2(x0, x1);
                s2  = add2(s2, xp);
                am2 = fma2(xp, we2, am2);
            }
            {   // edge B (e0+2 | e0+3)
                float d = mb.x, pd_ = mb.y;
                u64 t2  = fma2(nc1v, nsb, nra2);
                u64 we2 = mul2(pk2(pd_, pd_), mul2(t2, t2));
                float ind0 = (d > lo0 && d < hi0) ? vbm : 0.f;
                float ind1 = (d > lo1 && d < hi1) ? vbm : 0.f;
                u64 ind2 = pk2(ind0, ind1);
                cnt2 = add2(cnt2, ind2);
                ai2  = fma2(ind2, we2, ai2);
                float x0 = ex2f(fmaf(sl20, d, ic20)) * vbm;
                float x1 = ex2f(fmaf(sl21, d, ic21)) * vbm;
                u64 xp = pk2(x0, x1);
                s2  = add2(s2, xp);
                am2 = fma2(xp, we2, am2);
            }
        }

        // combine the two half-warps (same features, disjoint edge subsets)
        cnt2 = add2(cnt2, __shfl_xor_sync(FULLMASK, cnt2, 16));
        ai2  = add2(ai2,  __shfl_xor_sync(FULLMASK, ai2,  16));
        s2   = add2(s2,   __shfl_xor_sync(FULLMASK, s2,   16));
        am2  = add2(am2,  __shfl_xor_sync(FULLMASK, am2,  16));

        if (lane < 16) {
            float c0, c1f, a0, a1, ss0, ss1, m0, m1;
            upk2(cnt2, c0, c1f); upk2(ai2, a0, a1);
            upk2(s2, ss0, ss1);  upk2(am2, m0, m1);
            float g0, g1;
            if (f0 < KIND) {
                g0 = __fdividef(a0, c0 + 1e-5f);
                g1 = __fdividef(a1, c1f + 1e-5f);
            } else {
                g0 = (ss0 > 0.f) ? __fdividef(m0, ss0) : 0.f;
                g1 = (ss1 > 0.f) ? __fdividef(m1, ss1) : 0.f;
            }
            *(float2*)(g_gath + n * KTOT + f0) = make_float2(g0, g1);
        }
        return;
    }

    // ---------------- generic fallback (any b, multi-interval PWL) ----------
    int niv = g_niv;
    for (int i = tid; i <= niv; i += blockDim.x) sB[i] = g_B[i];
    for (int i = tid; i < niv * KMLP; i += blockDim.x) { sSl[i] = g_slope[i]; sIc[i] = g_icept[i]; }
    __syncthreads();

    int n = blockIdx.x * WARPS + w;
    if (n >= n_nodes) return;
    const float ac = g_ac, c1 = g_c1, bc = g_bc;
    const float lo_b = (float)lane * binw;
    const float hi_b = lo_b + binw;
    const int mk = lane & (KMLP - 1);

    float nval = nodes[n * KTOT + lane];
    float nra  = ac * nval;
    int start = g_row_ptr[n], end = g_row_ptr[n + 1];
    const float* nl = nodes + lane;

    float cnt = 0.f, ai = 0.f, am = 0.f, s = 0.f, m = -INFINITY;
    for (int e = start; e < end; e++) {
        float d   = __ldg(&dist[e]);
        float pp  = __ldg(&pad[e]);
        int   sid = __ldg(&send[e]);
        float nsv = __ldg(nl + sid * KTOT);
        float t   = fmaf(-c1, nsv, nra);
        float we  = pp * powf(fabsf(t), bc);
        if ((d > lo_b) && (d < hi_b)) { cnt += 1.f; ai += we; }
        int lo = 0, hi = niv - 1;
        while (lo < hi) {
            int mid = (lo + hi + 1) >> 1;
            if (d >= sB[mid]) lo = mid; else hi = mid - 1;
        }
        float v  = fmaf(sSl[lo * KMLP + mk], d, sIc[lo * KMLP + mk]);
        float nm = fmaxf(m, v);
        float sc = __expf(m - nm);
        float p  = __expf(v - nm);
        s  = fmaf(s, sc, p);
        am = fmaf(am, sc, p * we);
        m  = nm;
    }
    float g;
    if (lane < KIND) g = __fdividef(ai, cnt + 1e-5f);
    else             g = (s > 0.f) ? __fdividef(am, s) : 0.f;
    g_gath[n * KTOT + lane] = g;
}

// ---------------- epilogue: out = relu(nodes@WS + gath@WG + bg) --------------
__global__ void __launch_bounds__(WARPS * 32)
epi_kernel(const float* __restrict__ nodes, const float* __restrict__ wgs,
           const float* __restrict__ wgg,   const float* __restrict__ bgg,
           float* __restrict__ out, int n_nodes) {
    __shared__ float4 sX[WARPS][8][8];
    __shared__ float4 sG[WARPS][8][8];

    int tid = threadIdx.x;
    int w = tid >> 5, lane = tid & 31;

    float ws[KTOT], wg[KTOT];
    #pragma unroll
    for (int j = 0; j < KTOT; j++) {
        ws[j] = __ldg(&wgs[j * KTOT + lane]);
        wg[j] = __ldg(&wgg[j * KTOT + lane]);
    }
    float bgk = __ldg(&bgg[lane]);

    int wid = blockIdx.x * WARPS + w;
    int n0 = wid * 8;
    if (n0 >= n_nodes) return;

    const float4* x4 = (const float4*)nodes;
    const float4* g4 = (const float4*)g_gath;
    int lim4 = n_nodes * 8;
    {
        int i1 = lane >> 3, j1 = lane & 7;
        int idxA = n0 * 8 + lane, idxB = idxA + 32;
        float4 z = make_float4(0.f, 0.f, 0.f, 0.f);
        sX[w][i1][j1]     = (idxA < lim4) ? __ldg(&x4[idxA]) : z;
        sX[w][i1 + 4][j1] = (idxB < lim4) ? __ldg(&x4[idxB]) : z;
        sG[w][i1][j1]     = (idxA < lim4) ? __ldg(&g4[idxA]) : z;
        sG[w][i1 + 4][j1] = (idxB < lim4) ? __ldg(&g4[idxB]) : z;
    }
    __syncwarp();

    #pragma unroll
    for (int i = 0; i < 8; i++) {
        int n = n0 + i;
        if (n >= n_nodes) break;
        float o = bgk;
        #pragma unroll
        for (int j4 = 0; j4 < 8; j4++) {
            float4 xv = sX[w][i][j4];
            float4 gv = sG[w][i][j4];
            o = fmaf(xv.x, ws[j4 * 4 + 0], o);
            o = fmaf(xv.y, ws[j4 * 4 + 1], o);
            o = fmaf(xv.z, ws[j4 * 4 + 2], o);
            o = fmaf(xv.w, ws[j4 * 4 + 3], o);
            o = fmaf(gv.x, wg[j4 * 4 + 0], o);
            o = fmaf(gv.y, wg[j4 * 4 + 1], o);
            o = fmaf(gv.z, wg[j4 * 4 + 2], o);
            o = fmaf(gv.w, wg[j4 * 4 + 3], o);
        }
        out[n * KTOT + lane] = fmaxf(o, 0.f);
    }
}

// ---------------- launch ----------------
extern "C" void kernel_launch(void* const* d_in, const int* in_sizes, int n_in,
                              void* d_out, int out_size) {
    const float* nodes     = (const float*)d_in[0];
    const float* distance  = (const float*)d_in[1];
    const float* padding   = (const float*)d_in[2];
    const int*   receivers = (const int*)d_in[3];
    const int*   senders   = (const int*)d_in[4];
    const float* w1        = (const float*)d_in[5];
    const float* b1        = (const float*)d_in[6];
    const float* w2        = (const float*)d_in[7];
    const float* b2        = (const float*)d_in[8];
    const float* a         = (const float*)d_in[9];
    const float* b         = (const float*)d_in[10];
    const float* wgs       = (const float*)d_in[11];
    const float* wgg       = (const float*)d_in[12];
    const float* bgg       = (const float*)d_in[13];

    int n_nodes = in_sizes[0] / KTOT;
    int n_edges = in_sizes[1];
    int meta_ok = (n_edges <= MAXEDGES) ? 1 : 0;

    int pblocks = (n_edges + 255) / 256;
    if (pblocks < 1) pblocks = 1;
    pre_kernel<<<pblocks, 256>>>(w1, b1, w2, b2, a, b,
                                 distance, padding, senders, receivers,
                                 n_edges, n_nodes, meta_ok);

    int gblocks = (n_nodes + WARPS - 1) / WARPS;
    gather_kernel<<<gblocks, WARPS * 32>>>(nodes, distance, padding, senders, n_nodes);

    int nwarps = (n_nodes + 7) / 8;
    int eblocks = (nwarps + WARPS - 1) / WARPS;
    epi_kernel<<<eblocks, WARPS * 32>>>(nodes, wgs, wgg, bgg, (float*)d_out, n_nodes);
}

// round 5
// speedup vs baseline: 1.7899x; 1.2037x over previous
#include <cuda_runtime.h>
#include <math.h>

#define KTOT 32
#define KIND 16
#define KMLP 16
#define DH   64
#define DISTMAX 1.0f
#define MAXNODES 100001
#define MAXIV 65
#define WARPS 8
#define FULLMASK 0xffffffffu

// ---------------- device scratch ----------------
__device__ int   g_row_ptr[MAXNODES + 2];
__device__ float g_B[MAXIV + 1];
__device__ int   g_niv;
__device__ float g_slope[MAXIV * KMLP];
__device__ float g_icept[MAXIV * KMLP];
__device__ float g_ac, g_c1, g_bc;
__device__ int   g_fast;
__device__ __align__(16) float g_gath[MAXNODES * KTOT];
// interleaved node features: g_nodesT[n*32 + 2*f] = nodes[n][f], [..+1] = nodes[n][f+16]
__device__ __align__(16) float g_nodesT[MAXNODES * KTOT];

// ---------------- packed f32x2 helpers ----------------
typedef unsigned long long u64;
__device__ __forceinline__ u64 pk2(float lo, float hi) {
    u64 r; asm("mov.b64 %0,{%1,%2};" : "=l"(r) : "f"(lo), "f"(hi)); return r;
}
__device__ __forceinline__ void upk2(u64 v, float& lo, float& hi) {
    asm("mov.b64 {%0,%1},%2;" : "=f"(lo), "=f"(hi) : "l"(v));
}
__device__ __forceinline__ u64 fma2(u64 a, u64 b, u64 c) {
    u64 r; asm("fma.rn.f32x2 %0,%1,%2,%3;" : "=l"(r) : "l"(a), "l"(b), "l"(c)); return r;
}
__device__ __forceinline__ u64 mul2(u64 a, u64 b) {
    u64 r; asm("mul.rn.f32x2 %0,%1,%2;" : "=l"(r) : "l"(a), "l"(b)); return r;
}
__device__ __forceinline__ u64 add2(u64 a, u64 b) {
    u64 r; asm("add.rn.f32x2 %0,%1,%2;" : "=l"(r) : "l"(a), "l"(b)); return r;
}
__device__ __forceinline__ float ex2f(float x) {
    float r; asm("ex2.approx.f32 %0,%1;" : "=f"(r) : "f"(x)); return r;
}

// ---------------- pre-pass: rowptr scatter + interleaved transpose + PWL -----
__global__ void pre_kernel(const float* __restrict__ w1, const float* __restrict__ b1,
                           const float* __restrict__ w2, const float* __restrict__ b2,
                           const float* __restrict__ a,  const float* __restrict__ b,
                           const float* __restrict__ nodes,
                           const int* __restrict__ recv,
                           int n_edges, int n_nodes) {
    int t = blockIdx.x * blockDim.x + threadIdx.x;
    // rowptr via boundary scatter on sorted receivers
    if (t < n_edges) {
        int r = __ldg(&recv[t]);
        int rp = (t == 0) ? -1 : __ldg(&recv[t - 1]);
        for (int nn = rp + 1; nn <= r; nn++) g_row_ptr[nn] = t;
        if (t == n_edges - 1)
            for (int nn = r + 1; nn <= n_nodes; nn++) g_row_ptr[nn] = n_edges;
    }
    // interleaved transpose: (f, f+16) adjacent
    if (t < n_nodes * KIND) {
        int n = t >> 4, fl = t & 15;
        float va = __ldg(&nodes[n * KTOT + fl]);
        float vb = __ldg(&nodes[n * KTOT + KIND + fl]);
        *(float2*)(g_nodesT + n * KTOT + 2 * fl) = make_float2(va, vb);
    }
    if (blockIdx.x != 0) return;

    // ---- PWL setup (block 0) ----
    __shared__ float sw1[DH], sb1[DH], sw2[DH * KMLP], sb2[KMLP];
    __shared__ float bps[DH];
    __shared__ int   nbp;
    __shared__ float B[MAXIV + 1];
    __shared__ int   niv_s;
    int tid = threadIdx.x;
    for (int k = tid; k < DH; k += blockDim.x) { sw1[k] = w1[k]; sb1[k] = b1[k]; }
    for (int k = tid; k < DH * KMLP; k += blockDim.x) sw2[k] = w2[k];
    if (tid < KMLP) sb2[tid] = b2[tid];
    if (tid == 0) {
        float ac = fminf(fmaxf(a[0], 0.f), 1.f);
        g_ac = ac; g_c1 = 1.f - ac;
        g_bc = fabsf(b[0]);
        nbp = 0;
    }
    __syncthreads();
    if (tid < DH) {
        float w = sw1[tid], bb = sb1[tid];
        if (w != 0.f) {
            float tt = -bb / w;
            if (tt > 0.f && tt < DISTMAX) { int k = atomicAdd(&nbp, 1); bps[k] = tt; }
        }
    }
    __syncthreads();
    if (tid == 0) {
        for (int k = 1; k < nbp; k++) {
            float v = bps[k]; int j = k - 1;
            while (j >= 0 && bps[j] > v) { bps[j + 1] = bps[j]; j--; }
            bps[j + 1] = v;
        }
        B[0] = 0.f;
        for (int k = 0; k < nbp; k++) B[k + 1] = bps[k];
        B[nbp + 1] = DISTMAX;
        niv_s = nbp + 1;
        g_niv = niv_s;
        g_fast = (g_bc == 2.0f && niv_s == 1) ? 1 : 0;
    }
    __syncthreads();
    int niv = niv_s;
    for (int k = tid; k <= niv; k += blockDim.x) g_B[k] = B[k];
    for (int idx = tid; idx < niv * KMLP; idx += blockDim.x) {
        int iv = idx / KMLP, k = idx % KMLP;
        float dm = 0.5f * (B[iv] + B[iv + 1]);
        float sl = 0.f, ic = 0.f;
        for (int h = 0; h < DH; h++) {
            float w = sw1[h], bb = sb1[h];
            if (w * dm + bb > 0.f) {
                float w2v = sw2[h * KMLP + k];
                sl += w * w2v;
                ic += bb * w2v;
            }
        }
        g_slope[idx] = sl;
        g_icept[idx] = ic + sb2[k];
    }
}

// ---------------- gather: warp/node, half-warps = 2 edges, lane = (f, f+16) --
__global__ void __launch_bounds__(WARPS * 32)
gather_kernel(const float* __restrict__ nodes, const float* __restrict__ dist,
              const float* __restrict__ pad,   const int* __restrict__ send,
              int n_nodes) {
    __shared__ float sB[MAXIV + 1];
    __shared__ float sSl[MAXIV * KMLP], sIc[MAXIV * KMLP];

    int tid = threadIdx.x;
    const int w = tid >> 5, lane = tid & 31;
    const int fast = g_fast;
    const float binw = DISTMAX / (float)KIND;

    if (fast) {
        int n = blockIdx.x * WARPS + w;
        if (n >= n_nodes) return;

        const float ac = g_ac, c1 = g_c1;
        const int h  = lane >> 4;          // which edge of the pair
        const int fl = lane & 15;          // feature pair (fl, fl+16)
        const float lo_b = (float)fl * binw;
        const float hi_b = lo_b + binw;

        const float L2E = 1.4426950408889634f;
        float sl2 = __ldg(&g_slope[fl]) * L2E;
        float ic2 = -fmaxf(sl2 * DISTMAX, 0.f);   // per-lane constant base (cancels)

        int start = g_row_ptr[n], end = g_row_ptr[n + 1];
        u64 nr2  = __ldg((const u64*)(g_nodesT + n * KTOT + 2 * fl));
        u64 nra2 = mul2(pk2(ac, ac), nr2);
        u64 nc1v = pk2(-c1, -c1);
        const float* nT = g_nodesT + 2 * fl;

        u64 acc2 = 0ull, sums2 = 0ull;

        if (start < end) {
            // 1-deep software pipeline: meta+gather for next pair in flight
            int e0 = start;
            int ep = min(e0 + h, end - 1);
            float d0 = __ldg(&dist[ep]);
            float p0 = __ldg(&pad[ep]);
            int   s0 = __ldg(&send[ep]);
            float v0 = (e0 + h < end) ? 1.f : 0.f;
            u64  ns0 = __ldg((const u64*)(nT + s0 * KTOT));

            for (e0 += 2; e0 < end; e0 += 2) {
                int ep1 = min(e0 + h, end - 1);
                float d1 = __ldg(&dist[ep1]);
                float p1 = __ldg(&pad[ep1]);
                int   s1 = __ldg(&send[ep1]);
                float v1 = (e0 + h < end) ? 1.f : 0.f;
                u64  ns1 = __ldg((const u64*)(nT + s1 * KTOT));

                u64 t2  = fma2(nc1v, ns0, nra2);
                u64 we2 = mul2(pk2(p0, p0), mul2(t2, t2));
                float ind = ((d0 > lo_b) && (d0 < hi_b)) ? v0 : 0.f;
                float x   = ex2f(fmaf(sl2, d0, ic2)) * v0;
                u64 w2 = pk2(ind, x);
                acc2  = fma2(w2, we2, acc2);
                sums2 = add2(sums2, w2);

                d0 = d1; p0 = p1; v0 = v1; ns0 = ns1;
            }
            {   // drain
                u64 t2  = fma2(nc1v, ns0, nra2);
                u64 we2 = mul2(pk2(p0, p0), mul2(t2, t2));
                float ind = ((d0 > lo_b) && (d0 < hi_b)) ? v0 : 0.f;
                float x   = ex2f(fmaf(sl2, d0, ic2)) * v0;
                u64 w2 = pk2(ind, x);
                acc2  = fma2(w2, we2, acc2);
                sums2 = add2(sums2, w2);
            }
        }

        // combine half-warps (same features, disjoint edges)
        acc2  = add2(acc2,  __shfl_xor_sync(FULLMASK, acc2,  16));
        sums2 = add2(sums2, __shfl_xor_sync(FULLMASK, sums2, 16));

        if (lane < 16) {
            float ai, am, cnt, s;
            upk2(acc2, ai, am);
            upk2(sums2, cnt, s);
            float gi = __fdividef(ai, cnt + 1e-5f);
            float gm = (s > 0.f) ? __fdividef(am, s) : 0.f;
            g_gath[n * KTOT + fl] = gi;
            g_gath[n * KTOT + KIND + fl] = gm;
        }
        return;
    }

    // ---------------- generic fallback (any b, multi-interval PWL) ----------
    int niv = g_niv;
    for (int i = tid; i <= niv; i += blockDim.x) sB[i] = g_B[i];
    for (int i = tid; i < niv * KMLP; i += blockDim.x) { sSl[i] = g_slope[i]; sIc[i] = g_icept[i]; }
    __syncthreads();

    int n = blockIdx.x * WARPS + w;
    if (n >= n_nodes) return;
    const float ac = g_ac, c1 = g_c1, bc = g_bc;
    const float lo_b = (float)lane * binw;
    const float hi_b = lo_b + binw;
    const int mk = lane & (KMLP - 1);

    float nval = nodes[n * KTOT + lane];
    float nra  = ac * nval;
    int start = g_row_ptr[n], end = g_row_ptr[n + 1];
    const float* nl = nodes + lane;

    float cnt = 0.f, ai = 0.f, am = 0.f, s = 0.f, m = -INFINITY;
    for (int e = start; e < end; e++) {
        float d   = __ldg(&dist[e]);
        float pp  = __ldg(&pad[e]);
        int   sid = __ldg(&send[e]);
        float nsv = __ldg(nl + sid * KTOT);
        float t   = fmaf(-c1, nsv, nra);
        float we  = pp * powf(fabsf(t), bc);
        if ((d > lo_b) && (d < hi_b)) { cnt += 1.f; ai += we; }
        int lo = 0, hi = niv - 1;
        while (lo < hi) {
            int mid = (lo + hi + 1) >> 1;
            if (d >= sB[mid]) lo = mid; else hi = mid - 1;
        }
        float v  = fmaf(sSl[lo * KMLP + mk], d, sIc[lo * KMLP + mk]);
        float nm = fmaxf(m, v);
        float sc = __expf(m - nm);
        float p  = __expf(v - nm);
        s  = fmaf(s, sc, p);
        am = fmaf(am, sc, p * we);
        m  = nm;
    }
    float g;
    if (lane < KIND) g = __fdividef(ai, cnt + 1e-5f);
    else             g = (s > 0.f) ? __fdividef(am, s) : 0.f;
    g_gath[n * KTOT + lane] = g;
}

// ---------------- epilogue: out = relu(nodes@WS + gath@WG + bg) --------------
__global__ void __launch_bounds__(WARPS * 32)
epi_kernel(const float* __restrict__ nodes, const float* __restrict__ wgs,
           const float* __restrict__ wgg,   const float* __restrict__ bgg,
           float* __restrict__ out, int n_nodes) {
    __shared__ float4 sX[WARPS][8][8];
    __shared__ float4 sG[WARPS][8][8];

    int tid = threadIdx.x;
    int w = tid >> 5, lane = tid & 31;

    float ws[KTOT], wg[KTOT];
    #pragma unroll
    for (int j = 0; j < KTOT; j++) {
        ws[j] = __ldg(&wgs[j * KTOT + lane]);
        wg[j] = __ldg(&wgg[j * KTOT + lane]);
    }
    float bgk = __ldg(&bgg[lane]);

    int wid = blockIdx.x * WARPS + w;
    int n0 = wid * 8;
    if (n0 >= n_nodes) return;

    const float4* x4 = (const float4*)nodes;
    const float4* g4 = (const float4*)g_gath;
    int lim4 = n_nodes * 8;
    {
        int i1 = lane >> 3, j1 = lane & 7;
        int idxA = n0 * 8 + lane, idxB = idxA + 32;
        float4 z = make_float4(0.f, 0.f, 0.f, 0.f);
        sX[w][i1][j1]     = (idxA < lim4) ? __ldg(&x4[idxA]) : z;
        sX[w][i1 + 4][j1] = (idxB < lim4) ? __ldg(&x4[idxB]) : z;
        sG[w][i1][j1]     = (idxA < lim4) ? __ldg(&g4[idxA]) : z;
        sG[w][i1 + 4][j1] = (idxB < lim4) ? __ldg(&g4[idxB]) : z;
    }
    __syncwarp();

    #pragma unroll
    for (int i = 0; i < 8; i++) {
        int n = n0 + i;
        if (n >= n_nodes) break;
        float o = bgk;
        #pragma unroll
        for (int j4 = 0; j4 < 8; j4++) {
            float4 xv = sX[w][i][j4];
            float4 gv = sG[w][i][j4];
            o = fmaf(xv.x, ws[j4 * 4 + 0], o);
            o = fmaf(xv.y, ws[j4 * 4 + 1], o);
            o = fmaf(xv.z, ws[j4 * 4 + 2], o);
            o = fmaf(xv.w, ws[j4 * 4 + 3], o);
            o = fmaf(gv.x, wg[j4 * 4 + 0], o);
            o = fmaf(gv.y, wg[j4 * 4 + 1], o);
            o = fmaf(gv.z, wg[j4 * 4 + 2], o);
            o = fmaf(gv.w, wg[j4 * 4 + 3], o);
        }
        out[n * KTOT + lane] = fmaxf(o, 0.f);
    }
}

// ---------------- launch ----------------
extern "C" void kernel_launch(void* const* d_in, const int* in_sizes, int n_in,
                              void* d_out, int out_size) {
    const float* nodes     = (const float*)d_in[0];
    const float* distance  = (const float*)d_in[1];
    const float* padding   = (const float*)d_in[2];
    const int*   receivers = (const int*)d_in[3];
    const int*   senders   = (const int*)d_in[4];
    const float* w1        = (const float*)d_in[5];
    const float* b1        = (const float*)d_in[6];
    const float* w2        = (const float*)d_in[7];
    const float* b2        = (const float*)d_in[8];
    const float* a         = (const float*)d_in[9];
    const float* b         = (const float*)d_in[10];
    const float* wgs       = (const float*)d_in[11];
    const float* wgg       = (const float*)d_in[12];
    const float* bgg       = (const float*)d_in[13];

    int n_nodes = in_sizes[0] / KTOT;
    int n_edges = in_sizes[1];

    int pwork = n_edges > n_nodes * KIND ? n_edges : n_nodes * KIND;
    int pblocks = (pwork + 255) / 256;
    if (pblocks < 1) pblocks = 1;
    pre_kernel<<<pblocks, 256>>>(w1, b1, w2, b2, a, b, nodes,
                                 receivers, n_edges, n_nodes);

    int gblocks = (n_nodes + WARPS - 1) / WARPS;
    gather_kernel<<<gblocks, WARPS * 32>>>(nodes, distance, padding, senders, n_nodes);

    int nwarps = (n_nodes + 7) / 8;
    int eblocks = (nwarps + WARPS - 1) / WARPS;
    epi_kernel<<<eblocks, WARPS * 32>>>(nodes, wgs, wgg, bgg, (float*)d_out, n_nodes);
}